// round 10
// baseline (speedup 1.0000x reference)
#include <cuda_runtime.h>

#define IMG_H 512
#define IMG_W 512
#define RPB   32
#define KRAD  15
#define INV_KK (1.0f/961.0f)
#define TPB   128
#define NW    4
#define FULL  0xffffffffu

__device__ double g_acc[3];
__device__ unsigned int g_count;

#define VADD(ptr)  do { \
    if (validA) { float4 _v = *(const float4*)(ptr); \
        a0 += _v.x; a1 += _v.y; a2 += _v.z; a3 += _v.w; } \
    if (validB) { float4 _v = *(const float4*)((ptr) + 128); \
        b0 += _v.x; b1 += _v.y; b2 += _v.z; b3 += _v.w; } } while (0)

#define VSUB(ptr)  do { \
    if (validA) { float4 _v = *(const float4*)(ptr); \
        a0 -= _v.x; a1 -= _v.y; a2 -= _v.z; a3 -= _v.w; } \
    if (validB) { float4 _v = *(const float4*)((ptr) + 128); \
        b0 -= _v.x; b1 -= _v.y; b2 -= _v.z; b3 -= _v.w; } } while (0)

// Windowed 8-chunk box sum + fused elementwise accumulation.
__device__ __forceinline__ void scan_and_accum(
    float a0, float a1, float a2, float a3,
    float b0, float b1, float b2, float b3,
    float4 xc, float4 tc, int lane,
    float& r0, float& r1, float& r2)
{
    float A01 = a0 + a1, A012 = A01 + a2;
    float Qown = A012 + a3;
    float B01 = b0 + b1, B012 = B01 + b2;
    float QB   = B012 + b3;

    // truncated suffix window over A chunk totals: sum Q[lane..min(lane+7,31)]
    float s = Qown;
    {
        float nb = __shfl_down_sync(FULL, s, 1);  if (lane + 1 < 32) s += nb;
        nb = __shfl_down_sync(FULL, s, 2);        if (lane + 2 < 32) s += nb;
        nb = __shfl_down_sync(FULL, s, 4);        if (lane + 4 < 32) s += nb;
    }
    // inclusive prefix of B chunk totals over lanes 0..7 (parallel chain)
    float p = QB;
    {
        float nb = __shfl_up_sync(FULL, p, 1);  if (lane >= 1) p += nb;
        nb = __shfl_up_sync(FULL, p, 2);        if (lane >= 2) p += nb;
        nb = __shfl_up_sync(FULL, p, 4);        if (lane >= 4) p += nb;
    }
    float pbv = __shfl_sync(FULL, p, max(lane - 25, 0));
    float W8  = s + ((lane >= 25) ? pbv : 0.f);

    // leading prefixes of chunk lane+8 (A for lane<24, else B chunk lane-24)
    float fa0 = __shfl_sync(FULL, a0,   lane + 8);
    float fa1 = __shfl_sync(FULL, A01,  lane + 8);
    float fa2 = __shfl_sync(FULL, A012, lane + 8);
    float fb0 = __shfl_sync(FULL, b0,   max(lane - 24, 0));
    float fb1 = __shfl_sync(FULL, B01,  max(lane - 24, 0));
    float fb2 = __shfl_sync(FULL, B012, max(lane - 24, 0));
    float f0   = (lane < 24) ? fa0 : fb0;
    float f01  = (lane < 24) ? fa1 : fb1;
    float f012 = (lane < 24) ? fa2 : fb2;

    float wsv[4] = { W8 - a0, W8 - A01 + f0, W8 - A012 + f01, W8 - Qown + f012 };
    float xv[4]  = { xc.x, xc.y, xc.z, xc.w };
    float tv[4]  = { tc.x, tc.y, tc.z, tc.w };

    #pragma unroll
    for (int j = 0; j < 4; ++j) {
        float x = xv[j], t = tv[j];
        float e   = __expf(-fabsf(x));
        float l1p = __logf(1.0f + e);
        float bce = l1p + fmaxf(x, 0.f) - t * x;
        float rp  = __fdividef(1.0f, 1.0f + e);
        float p_  = (x >= 0.f) ? rp : e * rp;
        float weit = 1.0f + 5.0f * fabsf(wsv[j] * INV_KK - t);
        r0 += weit * bce;
        r1 += p_ * t * weit;
        r2 += (p_ + t) * weit;
    }
}

__global__ __launch_bounds__(TPB) void wiou_bce_main(
    const float* __restrict__ X,   // logits
    const float* __restrict__ T,   // targets
    float* __restrict__ out, int nblocks, double inv_count)
{
    __shared__ float red[NW][3];

    const int tid  = threadIdx.x;
    const int lane = tid & 31;
    const int w    = tid >> 5;

    const int bpi = IMG_H / RPB;            // 16 strips per image
    const int n   = blockIdx.x / bpi;
    const int y0  = (blockIdx.x % bpi) * RPB;

    const float* Tn = T + (size_t)n * IMG_H * IMG_W;
    const float* Xn = X + (size_t)n * IMG_H * IMG_W;

    const int colA = w * 128 - 16 + lane * 4;
    const bool validA = !(w == 0 && lane < 4);
    const bool validB = (lane < 8) && !(w == 3 && lane >= 4);

    float a0 = 0.f, a1 = 0.f, a2 = 0.f, a3 = 0.f;
    float b0 = 0.f, b1 = 0.f, b2 = 0.f, b3 = 0.f;

    // ---- prologue: rows [y0-15, y0+14] ----
    {
        int klo = (y0 - KRAD < 0) ? 0 : (y0 - KRAD);
        const float* row = Tn + (ptrdiff_t)klo * IMG_W + colA;
        for (int yy = klo; yy <= y0 + KRAD - 1; ++yy) {
            VADD(row);
            row += IMG_W;
        }
    }

    float r0 = 0.f, r1 = 0.f, r2 = 0.f;

    // pA = &T[y+15][colA]; retire offsets negative, center T = (u-15)*W + 16.
    const float* pA = Tn + (ptrdiff_t)(y0 + KRAD) * IMG_W + colA;
    const float* pX = Xn + (ptrdiff_t)y0 * IMG_W + (colA + 16);

    #pragma unroll 1
    for (int r = 0; r < RPB; r += 4) {
        const int y = y0 + r;

        // batch all center loads up front (8 independent LDG.128)
        float4 xcv[4], tcv[4];
        #pragma unroll
        for (int u = 0; u < 4; ++u) {
            xcv[u] = __ldcs((const float4*)(pX + u * IMG_W));
            tcv[u] = *(const float4*)(pA + (u - 15) * IMG_W + 16);
        }

        #pragma unroll
        for (int u = 0; u < 4; ++u) {
            // retire row (y+u-16) before extending for row y+u (u>=1)
            if (u > 0 && (y + u - 16) >= 0) VSUB(pA + (u - 31) * IMG_W);
            // add row y+15+u
            if ((y + KRAD + u) < IMG_H)     VADD(pA + u * IMG_W);
            scan_and_accum(a0,a1,a2,a3, b0,b1,b2,b3, xcv[u], tcv[u], lane, r0, r1, r2);
        }

        // final retire: row y-12, preparing window for row y+4
        if ((y - 12) >= 0) VSUB(pA - 27 * IMG_W);

        pA += 4 * IMG_W; pX += 4 * IMG_W;
    }

    // ---- block reduction ----
    #pragma unroll
    for (int off = 16; off > 0; off >>= 1) {
        r0 += __shfl_down_sync(FULL, r0, off);
        r1 += __shfl_down_sync(FULL, r1, off);
        r2 += __shfl_down_sync(FULL, r2, off);
    }
    if (lane == 0) { red[w][0] = r0; red[w][1] = r1; red[w][2] = r2; }
    __syncthreads();

    if (tid == 0) {
        float s0 = red[0][0] + red[1][0] + red[2][0] + red[3][0];
        float s1 = red[0][1] + red[1][1] + red[2][1] + red[3][1];
        float s2 = red[0][2] + red[1][2] + red[2][2] + red[3][2];
        atomicAdd(&g_acc[0], (double)s0);
        atomicAdd(&g_acc[1], (double)s1);
        atomicAdd(&g_acc[2], (double)s2);
        __threadfence();
        unsigned int old = atomicAdd(&g_count, 1u);
        if (old == (unsigned int)(nblocks - 1)) {
            __threadfence();
            double d0 = g_acc[0], d1 = g_acc[1], d2 = g_acc[2];
            double wbce = d0 * inv_count;
            double uni  = d2 - d1;
            double wiou = 1.0 - (d1 + 1.0) / (uni + 1.0);
            out[0] = (float)(wbce + wiou);
            g_acc[0] = 0.0; g_acc[1] = 0.0; g_acc[2] = 0.0;
            g_count = 0u;
        }
    }
}

extern "C" void kernel_launch(void* const* d_in, const int* in_sizes, int n_in,
                              void* d_out, int out_size) {
    const float* X = (const float*)d_in[0];
    const float* T = (const float*)d_in[1];
    float* out = (float*)d_out;

    const int n_elem = in_sizes[0];
    const int imgs   = n_elem / (IMG_H * IMG_W);
    const int nb     = imgs * (IMG_H / RPB);

    wiou_bce_main<<<nb, TPB>>>(X, T, out, nb, 1.0 / (double)n_elem);
}

// round 11
// speedup vs baseline: 1.0674x; 1.0674x over previous
#include <cuda_runtime.h>

#define IMG_H 512
#define IMG_W 512
#define RPB   32
#define KRAD  15
#define INV_KK (1.0f/961.0f)
#define TPB   128
#define NW    4
#define FULL  0xffffffffu

__device__ double g_acc[3];
__device__ unsigned int g_count;

// Windowed 8-chunk box sum (linear in its 8 inputs). Produces the 31-wide
// horizontal window sums for the 4 owned columns.
__device__ __forceinline__ void window8(
    float a0, float a1, float a2, float a3,
    float b0, float b1, float b2, float b3,
    int lane, float wsv[4])
{
    float A01 = a0 + a1, A012 = A01 + a2;
    float Qown = A012 + a3;
    float B01 = b0 + b1, B012 = B01 + b2;
    float QB   = B012 + b3;

    // truncated suffix window over A chunk totals: sum Q[lane..min(lane+7,31)]
    float s = Qown;
    {
        float nb = __shfl_down_sync(FULL, s, 1);  if (lane + 1 < 32) s += nb;
        nb = __shfl_down_sync(FULL, s, 2);        if (lane + 2 < 32) s += nb;
        nb = __shfl_down_sync(FULL, s, 4);        if (lane + 4 < 32) s += nb;
    }
    // inclusive prefix of B chunk totals over lanes 0..7 (parallel chain)
    float p = QB;
    {
        float nb = __shfl_up_sync(FULL, p, 1);  if (lane >= 1) p += nb;
        nb = __shfl_up_sync(FULL, p, 2);        if (lane >= 2) p += nb;
        nb = __shfl_up_sync(FULL, p, 4);        if (lane >= 4) p += nb;
    }
    float pbv = __shfl_sync(FULL, p, max(lane - 25, 0));
    float W8  = s + ((lane >= 25) ? pbv : 0.f);

    // leading prefixes of chunk lane+8 (A for lane<24, else B chunk lane-24)
    float fa0 = __shfl_sync(FULL, a0,   lane + 8);
    float fa1 = __shfl_sync(FULL, A01,  lane + 8);
    float fa2 = __shfl_sync(FULL, A012, lane + 8);
    float fb0 = __shfl_sync(FULL, b0,   max(lane - 24, 0));
    float fb1 = __shfl_sync(FULL, B01,  max(lane - 24, 0));
    float fb2 = __shfl_sync(FULL, B012, max(lane - 24, 0));
    float f0   = (lane < 24) ? fa0 : fb0;
    float f01  = (lane < 24) ? fa1 : fb1;
    float f012 = (lane < 24) ? fa2 : fb2;

    wsv[0] = W8 - a0;
    wsv[1] = W8 - A01  + f0;
    wsv[2] = W8 - A012 + f01;
    wsv[3] = W8 - Qown + f012;
}

__device__ __forceinline__ void accum_pixels(
    const float wsv[4], float4 xc, float4 tc,
    float& r0, float& r1, float& r2)
{
    float xv[4] = { xc.x, xc.y, xc.z, xc.w };
    float tv[4] = { tc.x, tc.y, tc.z, tc.w };
    #pragma unroll
    for (int j = 0; j < 4; ++j) {
        float x = xv[j], t = tv[j];
        float e   = __expf(-fabsf(x));
        float l1p = __logf(1.0f + e);
        float bce = l1p + fmaxf(x, 0.f) - t * x;
        float rp  = __fdividef(1.0f, 1.0f + e);
        float p_  = (x >= 0.f) ? rp : e * rp;
        float weit = 1.0f + 5.0f * fabsf(wsv[j] * INV_KK - t);
        r0 += weit * bce;
        r1 += p_ * t * weit;
        r2 += (p_ + t) * weit;
    }
}

__global__ __launch_bounds__(TPB, 7) void wiou_bce_main(
    const float* __restrict__ X,   // logits
    const float* __restrict__ T,   // targets
    float* __restrict__ out, int nblocks, double inv_count)
{
    __shared__ float red[NW][3];

    const int tid  = threadIdx.x;
    const int lane = tid & 31;
    const int w    = tid >> 5;

    const int bpi = IMG_H / RPB;            // 16 strips per image
    const int n   = blockIdx.x / bpi;
    const int y0  = (blockIdx.x % bpi) * RPB;

    const float* Tn = T + (size_t)n * IMG_H * IMG_W;
    const float* Xn = X + (size_t)n * IMG_H * IMG_W;

    const int colA = w * 128 - 16 + lane * 4;
    const bool validA = !(w == 0 && lane < 4);
    const bool validB = (lane < 8) && !(w == 3 && lane >= 4);

    // vertical sliding sums (basis "vs"; renamed w* inside the loop)
    float va0 = 0.f, va1 = 0.f, va2 = 0.f, va3 = 0.f;
    float vb0 = 0.f, vb1 = 0.f, vb2 = 0.f, vb3 = 0.f;

    // ---- prologue: rows [y0-15, y0+14] ----
    {
        int klo = (y0 - KRAD < 0) ? 0 : (y0 - KRAD);
        const float* row = Tn + (ptrdiff_t)klo * IMG_W + colA;
        for (int yy = klo; yy <= y0 + KRAD - 1; ++yy) {
            if (validA) { float4 v = *(const float4*)row;
                va0 += v.x; va1 += v.y; va2 += v.z; va3 += v.w; }
            if (validB) { float4 v = *(const float4*)(row + 128);
                vb0 += v.x; vb1 += v.y; vb2 += v.z; vb3 += v.w; }
            row += IMG_W;
        }
    }

    float r0 = 0.f, r1 = 0.f, r2 = 0.f;

    // pA = &T[y+15][colA]; retire = -30W/-29W, center T = -15W/-14W + 16.
    const float* pA = Tn + (ptrdiff_t)(y0 + KRAD) * IMG_W + colA;
    const float* pX = Xn + (ptrdiff_t)y0 * IMG_W + (colA + 16);

    #pragma unroll 1
    for (int r = 0; r < RPB; r += 2) {
        const int y = y0 + r;
        const bool ga1 = (y + KRAD)     < IMG_H;
        const bool ga2 = (y + KRAD + 1) < IMG_H;
        const bool gr1 = (y - KRAD)     >= 0;
        const bool gr2 = (y - KRAD + 1) >= 0;

        // ---- ALL loads batched at iteration top (max MLP) ----
        float4 xc1 = __ldcs((const float4*)pX);
        float4 xc2 = __ldcs((const float4*)(pX + IMG_W));
        float4 tc1 = *(const float4*)(pA - 15 * IMG_W + 16);
        float4 tc2 = *(const float4*)(pA - 14 * IMG_W + 16);

        // w = vs + add1   (basis for row y's window)
        if (ga1) {
            if (validA) { float4 v = *(const float4*)pA;
                va0 += v.x; va1 += v.y; va2 += v.z; va3 += v.w; }
            if (validB) { float4 v = *(const float4*)(pA + 128);
                vb0 += v.x; vb1 += v.y; vb2 += v.z; vb3 += v.w; }
        }
        // delta = add2 - ret1   (row y+1 basis = w + delta) -- independent of w
        float da0 = 0.f, da1 = 0.f, da2 = 0.f, da3 = 0.f;
        float db0 = 0.f, db1 = 0.f, db2 = 0.f, db3 = 0.f;
        if (ga2) {
            if (validA) { float4 v = *(const float4*)(pA + IMG_W);
                da0 += v.x; da1 += v.y; da2 += v.z; da3 += v.w; }
            if (validB) { float4 v = *(const float4*)(pA + IMG_W + 128);
                db0 += v.x; db1 += v.y; db2 += v.z; db3 += v.w; }
        }
        if (gr1) {
            if (validA) { float4 v = *(const float4*)(pA - 30 * IMG_W);
                da0 -= v.x; da1 -= v.y; da2 -= v.z; da3 -= v.w; }
            if (validB) { float4 v = *(const float4*)(pA - 30 * IMG_W + 128);
                db0 -= v.x; db1 -= v.y; db2 -= v.z; db3 -= v.w; }
        }

        // ---- two INDEPENDENT scan chains (overlap in the pipeline) ----
        float wsv1[4], wsvd[4];
        window8(va0,va1,va2,va3, vb0,vb1,vb2,vb3, lane, wsv1);
        window8(da0,da1,da2,da3, db0,db1,db2,db3, lane, wsvd);
        float wsv2[4] = { wsv1[0]+wsvd[0], wsv1[1]+wsvd[1],
                          wsv1[2]+wsvd[2], wsv1[3]+wsvd[3] };

        accum_pixels(wsv1, xc1, tc1, r0, r1, r2);
        accum_pixels(wsv2, xc2, tc2, r0, r1, r2);

        // fold ret2 into delta, then advance basis: vs_next = w + delta
        if (gr2) {
            if (validA) { float4 v = *(const float4*)(pA - 29 * IMG_W);
                da0 -= v.x; da1 -= v.y; da2 -= v.z; da3 -= v.w; }
            if (validB) { float4 v = *(const float4*)(pA - 29 * IMG_W + 128);
                db0 -= v.x; db1 -= v.y; db2 -= v.z; db3 -= v.w; }
        }
        va0 += da0; va1 += da1; va2 += da2; va3 += da3;
        vb0 += db0; vb1 += db1; vb2 += db2; vb3 += db3;

        pA += 2 * IMG_W; pX += 2 * IMG_W;
    }

    // ---- block reduction ----
    #pragma unroll
    for (int off = 16; off > 0; off >>= 1) {
        r0 += __shfl_down_sync(FULL, r0, off);
        r1 += __shfl_down_sync(FULL, r1, off);
        r2 += __shfl_down_sync(FULL, r2, off);
    }
    if (lane == 0) { red[w][0] = r0; red[w][1] = r1; red[w][2] = r2; }
    __syncthreads();

    if (tid == 0) {
        float s0 = red[0][0] + red[1][0] + red[2][0] + red[3][0];
        float s1 = red[0][1] + red[1][1] + red[2][1] + red[3][1];
        float s2 = red[0][2] + red[1][2] + red[2][2] + red[3][2];
        atomicAdd(&g_acc[0], (double)s0);
        atomicAdd(&g_acc[1], (double)s1);
        atomicAdd(&g_acc[2], (double)s2);
        __threadfence();
        unsigned int old = atomicAdd(&g_count, 1u);
        if (old == (unsigned int)(nblocks - 1)) {
            __threadfence();
            double d0 = g_acc[0], d1 = g_acc[1], d2 = g_acc[2];
            double wbce = d0 * inv_count;
            double uni  = d2 - d1;
            double wiou = 1.0 - (d1 + 1.0) / (uni + 1.0);
            out[0] = (float)(wbce + wiou);
            g_acc[0] = 0.0; g_acc[1] = 0.0; g_acc[2] = 0.0;
            g_count = 0u;
        }
    }
}

extern "C" void kernel_launch(void* const* d_in, const int* in_sizes, int n_in,
                              void* d_out, int out_size) {
    const float* X = (const float*)d_in[0];
    const float* T = (const float*)d_in[1];
    float* out = (float*)d_out;

    const int n_elem = in_sizes[0];
    const int imgs   = n_elem / (IMG_H * IMG_W);
    const int nb     = imgs * (IMG_H / RPB);

    wiou_bce_main<<<nb, TPB>>>(X, T, out, nb, 1.0 / (double)n_elem);
}